// round 2
// baseline (speedup 1.0000x reference)
#include <cuda_runtime.h>
#include <cstdint>

// LinearRationalSpline forward, sm_103a.
// inputs:  d_in[0] = inputs        [16384*64]      f32
//          d_in[1] = params_unnorm [16384*64, 63]  f32  (w:16, h:16, d:15, lam:16)
// output:  d_out = concat(outputs, logabsdet), each [16384*64] f32

#define NBINS 16
#define ROWP  63            // 4*NBINS - 1
#define TPB   128
#define BOUNDV 3.0f
#define MBW 0.001f
#define MBH 0.001f
#define MDRV 0.001f
#define MLAM 0.025f
#define EPSV 1e-6f

__device__ __forceinline__ float softplus_f(float v) {
    // stable: max(v,0) + log1p(exp(-|v|))
    return fmaxf(v, 0.0f) + log1pf(__expf(-fabsf(v)));
}

__global__ __launch_bounds__(TPB)
void lrs_kernel(const float* __restrict__ inputs,
                const float* __restrict__ params,
                float* __restrict__ out,
                int n) {
    __shared__ float sm[TPB * ROWP];   // 32256 B, 16B-divisible chunk per block

    const int tid = threadIdx.x;
    const long long base = (long long)blockIdx.x * (TPB * ROWP);

    // Coalesced float4 staging of this block's 128 rows (128*63 floats).
    const float4* __restrict__ g4 = reinterpret_cast<const float4*>(params + base);
    float4* s4 = reinterpret_cast<float4*>(sm);
    #pragma unroll
    for (int i = tid; i < TPB * ROWP / 4; i += TPB) s4[i] = g4[i];
    __syncthreads();

    const int gid = blockIdx.x * TPB + tid;
    const float x = inputs[gid];
    const float* __restrict__ row = sm + tid * ROWP;   // stride 63 -> conflict-free

    // ---------------- widths softmax + knots + bin search ----------------
    float w[NBINS];
    float sw = 0.0f;
    #pragma unroll
    for (int i = 0; i < NBINS; i++) { w[i] = __expf(row[i]); sw += w[i]; }
    const float wscale = (1.0f - MBW * (float)NBINS) / sw;
    #pragma unroll
    for (int i = 0; i < NBINS; i++) w[i] = fmaf(wscale, w[i], MBW);

    // knot_0 = -3; knot_j = -3 + 6*cumsum_j (j=1..15); knot_16 = +3
    int cnt = ((-BOUNDV + EPSV) <= x) ? 1 : 0;
    float cum = 0.0f;
    #pragma unroll
    for (int j = 1; j <= NBINS; j++) {
        cum += w[j - 1];
        float knot = (j == NBINS) ? BOUNDV : fmaf(6.0f, cum, -BOUNDV);
        cnt += ((knot + EPSV) <= x) ? 1 : 0;
    }
    int idx = cnt - 1;
    idx = idx < 0 ? 0 : (idx > NBINS - 1 ? NBINS - 1 : idx);

    // second pass: select knot[idx], knot[idx+1] (predicated, no dyn reg index)
    float klo = -BOUNDV, khi = BOUNDV;
    cum = 0.0f;
    #pragma unroll
    for (int j = 1; j <= NBINS; j++) {
        cum += w[j - 1];
        float knot = (j == NBINS) ? BOUNDV : fmaf(6.0f, cum, -BOUNDV);
        if (j == idx)     klo = knot;
        if (j == idx + 1) khi = knot;
    }
    const float cw   = klo;
    const float wsel = khi - klo;

    // ---------------- heights softmax + knot selection ----------------
    float sh = 0.0f;
    #pragma unroll
    for (int i = 0; i < NBINS; i++) { w[i] = __expf(row[NBINS + i]); sh += w[i]; }
    const float hscale = (1.0f - MBH * (float)NBINS) / sh;
    float hlo = -BOUNDV, hhi = BOUNDV;
    cum = 0.0f;
    #pragma unroll
    for (int j = 1; j <= NBINS; j++) {
        cum += fmaf(hscale, w[j - 1], MBH);
        float knot = (j == NBINS) ? BOUNDV : fmaf(6.0f, cum, -BOUNDV);
        if (j == idx)     hlo = knot;
        if (j == idx + 1) hhi = knot;
    }
    const float ch   = hlo;
    const float hsel = hhi - hlo;

    // ---------------- derivatives (padded edges) + lambda ----------------
    const float EDGE = 1.0f - MDRV;
    float d0, d1;
    if (idx == 0)          d0 = EDGE;
    else                   d0 = MDRV + softplus_f(row[2 * NBINS + idx - 1]);
    if (idx == NBINS - 1)  d1 = EDGE;
    else                   d1 = MDRV + softplus_f(row[2 * NBINS + idx]);

    const float lraw = row[3 * NBINS - 1 + idx];
    const float sig  = 1.0f / (1.0f + __expf(-lraw));
    const float lam  = fmaf(1.0f - 2.0f * MLAM, sig, MLAM);

    // ---------------- rational spline ----------------
    const float delta = hsel / wsel;
    const float wb  = sqrtf(d0 / d1);
    const float lwb = lam * wb;
    const float wc  = (lam * d0 + (wb - lwb) * d1) / delta;
    const float ya  = ch;
    const float yb  = ch + hsel;
    const float l1  = 1.0f - lam;
    const float yc  = (lwb * yb + l1 * ya) / (l1 + lwb);

    const float theta = (x - cw) / wsel;
    const bool  ind   = theta <= lam;
    const float lt    = lam - theta;

    const float wcyc      = wc * yc;
    const float wcyctheta = wcyc * theta;
    const float num = ind ? (wcyctheta + ya * lt)
                          : ((wcyc - wcyctheta) - wb * yb * lt);
    const float wctheta = wc * theta;
    const float den = ind ? (wctheta + lt)
                          : ((wc - wctheta) - wb * lt);

    float outv = num / den;
    const float dnum = wc * (ind ? lam * (yc - ya) : (wb - lwb) * (yb - yc)) / wsel;
    float lad = __logf(dnum) - 2.0f * __logf(fabsf(den));

    const bool outside = (x < -BOUNDV) || (x > BOUNDV);
    if (outside) { outv = x; lad = 0.0f; }

    out[gid]     = outv;
    out[n + gid] = lad;
}

extern "C" void kernel_launch(void* const* d_in, const int* in_sizes, int n_in,
                              void* d_out, int out_size) {
    const float* inputs = (const float*)d_in[0];
    const float* params = (const float*)d_in[1];
    float* out = (float*)d_out;
    const int n = in_sizes[0];                 // 16384*64 = 1,048,576
    const int blocks = n / TPB;                // divisible: 8192 blocks
    lrs_kernel<<<blocks, TPB>>>(inputs, params, out, n);
}

// round 3
// speedup vs baseline: 1.0245x; 1.0245x over previous
#include <cuda_runtime.h>
#include <cstdint>

// LinearRationalSpline forward, sm_103a.
// inputs:  d_in[0] = inputs        [16384*64]      f32
//          d_in[1] = params_unnorm [16384*64, 63]  f32  (w:16, h:16, d:15, lam:16)
// output:  d_out = concat(outputs, logabsdet), each [16384*64] f32
//
// R3: stage only w+h (32 floats/row) through smem (stride-33, conflict-free),
// gather d[idx-1], d[idx], lam[idx] directly via LDG after the bin search.
// Cuts DRAM read traffic ~11% and halves smem (32.25KB -> 16.9KB) -> occ 40->50%.

#define NBINS 16
#define ROWP  63            // 4*NBINS - 1
#define TPB   128
#define SMSTRIDE 33
#define BOUNDV 3.0f
#define MBW 0.001f
#define MBH 0.001f
#define MDRV 0.001f
#define MLAM 0.025f
#define EPSV 1e-6f

__device__ __forceinline__ float softplus_f(float v) {
    return fmaxf(v, 0.0f) + log1pf(__expf(-fabsf(v)));
}

__global__ __launch_bounds__(TPB, 8)
void lrs_kernel(const float* __restrict__ inputs,
                const float* __restrict__ params,
                float* __restrict__ out,
                int n) {
    __shared__ float sm[TPB * SMSTRIDE];   // 16896 B

    const int tid  = threadIdx.x;
    const int lane = tid & 31;
    const int warp = tid >> 5;
    const int gid  = blockIdx.x * TPB + tid;
    const long long blockRow = (long long)blockIdx.x * TPB;

    const float x = inputs[gid];

    // ---- stage w+h (first 32 floats of each row), coalesced per warp-instr ----
    // warp w handles rows [w*32, w*32+32); lane = element index 0..31.
    {
        const int r0 = warp * 32;
        #pragma unroll
        for (int k = 0; k < 32; k++) {
            const int r = r0 + k;
            sm[r * SMSTRIDE + lane] = params[(blockRow + r) * ROWP + lane];
        }
    }
    __syncthreads();

    const float* __restrict__ row = sm + tid * SMSTRIDE;  // (tid+c)%32 -> conflict-free
    const long long rbase = (long long)gid * ROWP;

    // ---------------- widths softmax + knots + bin search ----------------
    float w[NBINS];
    float sw = 0.0f;
    #pragma unroll
    for (int i = 0; i < NBINS; i++) { w[i] = __expf(row[i]); sw += w[i]; }
    const float wscale = (1.0f - MBW * (float)NBINS) * __fdividef(1.0f, sw);
    #pragma unroll
    for (int i = 0; i < NBINS; i++) w[i] = fmaf(wscale, w[i], MBW);

    // knot_0 = -3; knot_j = -3 + 6*cumsum_j (j=1..15); knot_16 = +3
    int cnt = ((-BOUNDV + EPSV) <= x) ? 1 : 0;
    float cum = 0.0f;
    #pragma unroll
    for (int j = 1; j <= NBINS; j++) {
        cum += w[j - 1];
        float knot = (j == NBINS) ? BOUNDV : fmaf(6.0f, cum, -BOUNDV);
        cnt += ((knot + EPSV) <= x) ? 1 : 0;
    }
    int idx = cnt - 1;
    idx = idx < 0 ? 0 : (idx > NBINS - 1 ? NBINS - 1 : idx);

    // ---- issue data-dependent gathers NOW; consumed after h-softmax ----
    const int i0 = (idx > 0)         ? (2 * NBINS + idx - 1) : 2 * NBINS;       // clamped addr
    const int i1 = (idx < NBINS - 1) ? (2 * NBINS + idx)     : (3 * NBINS - 2);
    const float d0raw = params[rbase + i0];
    const float d1raw = params[rbase + i1];
    const float lraw  = params[rbase + 3 * NBINS - 1 + idx];

    // second pass: select knot[idx], knot[idx+1] (predicated, no dyn reg index)
    float klo = -BOUNDV, khi = BOUNDV;
    cum = 0.0f;
    #pragma unroll
    for (int j = 1; j <= NBINS; j++) {
        cum += w[j - 1];
        float knot = (j == NBINS) ? BOUNDV : fmaf(6.0f, cum, -BOUNDV);
        if (j == idx)     klo = knot;
        if (j == idx + 1) khi = knot;
    }
    const float cw   = klo;
    const float wsel = khi - klo;

    // ---------------- heights softmax + knot selection ----------------
    float sh = 0.0f;
    #pragma unroll
    for (int i = 0; i < NBINS; i++) { w[i] = __expf(row[NBINS + i]); sh += w[i]; }
    const float hscale = (1.0f - MBH * (float)NBINS) * __fdividef(1.0f, sh);
    float hlo = -BOUNDV, hhi = BOUNDV;
    cum = 0.0f;
    #pragma unroll
    for (int j = 1; j <= NBINS; j++) {
        cum += fmaf(hscale, w[j - 1], MBH);
        float knot = (j == NBINS) ? BOUNDV : fmaf(6.0f, cum, -BOUNDV);
        if (j == idx)     hlo = knot;
        if (j == idx + 1) hhi = knot;
    }
    const float ch   = hlo;
    const float hsel = hhi - hlo;

    // ---------------- derivatives (padded edges) + lambda ----------------
    const float EDGE = 1.0f - MDRV;
    const float d0 = (idx == 0)         ? EDGE : (MDRV + softplus_f(d0raw));
    const float d1 = (idx == NBINS - 1) ? EDGE : (MDRV + softplus_f(d1raw));

    const float sig = __fdividef(1.0f, 1.0f + __expf(-lraw));
    const float lam = fmaf(1.0f - 2.0f * MLAM, sig, MLAM);

    // ---------------- rational spline ----------------
    const float delta = __fdividef(hsel, wsel);
    const float wb  = sqrtf(__fdividef(d0, d1));
    const float lwb = lam * wb;
    const float wc  = __fdividef(lam * d0 + (wb - lwb) * d1, delta);
    const float ya  = ch;
    const float yb  = ch + hsel;
    const float l1  = 1.0f - lam;
    const float yc  = __fdividef(lwb * yb + l1 * ya, l1 + lwb);

    const float theta = __fdividef(x - cw, wsel);
    const bool  ind   = theta <= lam;
    const float lt    = lam - theta;

    const float wcyc      = wc * yc;
    const float wcyctheta = wcyc * theta;
    const float num = ind ? (wcyctheta + ya * lt)
                          : ((wcyc - wcyctheta) - wb * yb * lt);
    const float wctheta = wc * theta;
    const float den = ind ? (wctheta + lt)
                          : ((wc - wctheta) - wb * lt);

    float outv = __fdividef(num, den);
    const float dnum = __fdividef(wc * (ind ? lam * (yc - ya) : (wb - lwb) * (yb - yc)), wsel);
    float lad = __logf(dnum) - 2.0f * __logf(fabsf(den));

    const bool outside = (x < -BOUNDV) || (x > BOUNDV);
    if (outside) { outv = x; lad = 0.0f; }

    out[gid]     = outv;
    out[n + gid] = lad;
}

extern "C" void kernel_launch(void* const* d_in, const int* in_sizes, int n_in,
                              void* d_out, int out_size) {
    const float* inputs = (const float*)d_in[0];
    const float* params = (const float*)d_in[1];
    float* out = (float*)d_out;
    const int n = in_sizes[0];                 // 16384*64 = 1,048,576
    const int blocks = n / TPB;                // 8192
    lrs_kernel<<<blocks, TPB>>>(inputs, params, out, n);
}